// round 7
// baseline (speedup 1.0000x reference)
#include <cuda_runtime.h>
#include <cstdint>

#define N_IMG 64
#define CH    64
#define KOUT  64
#define H     56
#define W     56
#define HW    (H*W)

// Packed quantized activations, pixel-major: byte((img*56+row)*64 + px)*64 + c
// px = j+1 (left pad at px=0); px 57..63 zero. 14.7 MB.
__device__ uint4 g_qa4[(size_t)N_IMG*56*64*64/16];
// Weights s8 packed as m16n8k32 B-fragments:
// uint4[(nt*9 + rs)*32 + lane] = {b0(ct2=0), b1(ct2=0), b0(ct2=1), b1(ct2=1)}
// b0 = w[oc = nt*8 + (lane>>2)][k = ct2*32 + 4*(lane&3) .. +3], b1 = same k+16
__device__ uint4 g_wq4[8*9*32];                 // 36 KB

__global__ __launch_bounds__(256)
void quant_fused_kernel(const float* __restrict__ x,
                        const float* __restrict__ w,
                        const float* __restrict__ scale_a,
                        const float* __restrict__ scale_w,
                        const float* __restrict__ zero_point) {
    const int t = threadIdx.x;
    if (blockIdx.y == 64) {
        // ---- weights ----
        const float sw = scale_w[0];
        for (int i = blockIdx.x*256 + t; i < KOUT*576; i += 56*256) {
            int m  = i / 576;
            int k  = i - m*576;
            int rs = k >> 6;
            int c  = k & 63;
            int r  = rs/3, s = rs - r*3;
            float wv = w[((m*CH + c)*3 + r)*3 + s];
            int iv = (int)rintf(__fmul_rn(wv, sw));
            iv = ((iv + 128) & 255) - 128;      // two's-complement s8 wrap
            int nt   = m >> 3;
            int g    = m & 7;
            int ct2  = c >> 5;
            int kk   = c & 31;
            int half = kk >> 4;
            int p    = (kk >> 2) & 3;
            int e    = kk & 3;
            size_t pos = ((size_t)((nt*9 + rs)*32 + g*4 + p)*4 + (ct2*2 + half))*4 + e;
            reinterpret_cast<int8_t*>(g_wq4)[pos] = (int8_t)iv;
        }
        return;
    }
    // ---- activations: one thread = 16 bytes (16 channels @ one pixel) ----
    const int row = blockIdx.x;
    const int img = blockIdx.y;
    const int px  = t >> 2;
    const int cg  = t & 3;
    const int c0  = cg*16;
    const int j   = px - 1;
    const float sa = scale_a[0];
    const float zp = zero_point[0];
    uint32_t wd[4] = {0u, 0u, 0u, 0u};
    if ((unsigned)j < (unsigned)W) {
        const float* xb = x + ((size_t)(img*CH + c0)*H + row)*W + j;
        #pragma unroll
        for (int w4 = 0; w4 < 4; ++w4) {
            uint32_t pk = 0;
            #pragma unroll
            for (int e = 0; e < 4; ++e) {
                float xv = xb[(w4*4 + e)*HW];
                float tq = __fadd_rn(__fmul_rn(xv, sa), -zp);   // match ref rounding
                float v  = fminf(fmaxf(rintf(tq), 0.f), 255.f) + zp;  // q_in + zp
                pk |= (uint32_t)((int)v & 255) << (e*8);
            }
            wd[w4] = pk;
        }
    }
    g_qa4[(size_t)((img*H + row)*64 + px)*4 + cg] =
        make_uint4(wd[0], wd[1], wd[2], wd[3]);
}

#define PXS   68                      // staged pixels per row
#define PSTR  80                      // pixel stride in smem bytes (bank-bijective)
#define SMEM_BYTES (4*PXS*PSTR)       // 21760 B

__global__ __launch_bounds__(256, 3)
void convq_kernel(const float* __restrict__ bias,
                  const float* __restrict__ scale_a,
                  const float* __restrict__ scale_w,
                  float* __restrict__ out) {
    extern __shared__ uint32_t smem[];

    const int tid  = threadIdx.x;
    const int lane = tid & 31;
    const int warp = tid >> 5;
    const int img  = blockIdx.y;
    const int q    = blockIdx.x;                // output rows 2q, 2q+1

    // ---- stage 4 input rows x 68 px x 64B via cp.async (zfill pads) ----
    {
        uint32_t sbase;
        asm("{ .reg .u64 tt; cvta.to.shared.u64 tt, %1; cvt.u32.u64 %0, tt; }"
            : "=r"(sbase) : "l"(smem));
        #pragma unroll
        for (int k = 0; k < 5; ++k) {
            int idx = tid + k*256;              // 0..1279, need 1088
            if (idx < 4*PXS*4) {
                int rowl = idx / (PXS*4);
                int rem  = idx - rowl*(PXS*4);
                int px   = rem >> 2;
                int c16  = rem & 3;
                int ir   = q*2 + rowl - 1;
                int ok   = ((unsigned)ir < (unsigned)H) && (px < 64);
                int sz   = ok ? 16 : 0;
                int irc  = min(max(ir, 0), H-1);
                int pxc  = min(px, 63);
                const char* src = reinterpret_cast<const char*>(g_qa4)
                    + (((size_t)((img*H + irc)*64 + pxc))*64 + c16*16);
                uint32_t dst = sbase + (rowl*PXS + px)*PSTR + c16*16;
                asm volatile("cp.async.cg.shared.global [%0], [%1], 16, %2;\n"
                             :: "r"(dst), "l"(src), "r"(sz) : "memory");
            }
        }
        asm volatile("cp.async.commit_group;\n" ::: "memory");
        asm volatile("cp.async.wait_group 0;\n" ::: "memory");
    }
    __syncthreads();

    // ---- GEMM: D[px=16 x oc=64] per warp; A=activations(smem), B=weights(L1) ----
    const int nh2 = warp >> 2;                  // output row: 2q + nh2
    const int P   = (warp & 3) * 16;            // pixel group base
    const int g   = lane >> 2;
    const int p   = lane & 3;

    int d[8][4];
    #pragma unroll
    for (int i = 0; i < 8; ++i) { d[i][0]=0; d[i][1]=0; d[i][2]=0; d[i][3]=0; }

    const uint4* wq = g_wq4 + lane;

    #pragma unroll
    for (int r = 0; r < 3; ++r) {
      #pragma unroll
      for (int s = 0; s < 3; ++s) {
        const int rs = r*3 + s;
        // a-frags: row of A = pixel P+s+g (+8); word = pxidx*20 + ct2*8 + khalf*4 + p
        const int rowb = ((nh2 + r)*PXS + P + s + g)*20 + p;
        uint32_t a00 = smem[rowb +   0];        // ct2=0, k0-15, px lo
        uint32_t a01 = smem[rowb + 160];        // ct2=0, k0-15, px hi (+8*20)
        uint32_t a02 = smem[rowb +   4];        // ct2=0, k16-31, px lo
        uint32_t a03 = smem[rowb + 164];
        uint32_t a10 = smem[rowb +   8];        // ct2=1
        uint32_t a11 = smem[rowb + 168];
        uint32_t a12 = smem[rowb +  12];
        uint32_t a13 = smem[rowb + 172];
        #pragma unroll
        for (int nt = 0; nt < 8; ++nt) {        // 8 oc-tiles
            uint4 b = wq[(nt*9 + rs)*32];       // LDG.128, L1-resident, static addr
            asm volatile(
              "mma.sync.aligned.m16n8k32.row.col.s32.s8.s8.s32 "
              "{%0,%1,%2,%3}, {%4,%5,%6,%7}, {%8,%9}, {%0,%1,%2,%3};\n"
              : "+r"(d[nt][0]), "+r"(d[nt][1]), "+r"(d[nt][2]), "+r"(d[nt][3])
              : "r"(a00), "r"(a01), "r"(a02), "r"(a03), "r"(b.x), "r"(b.y));
            asm volatile(
              "mma.sync.aligned.m16n8k32.row.col.s32.s8.s8.s32 "
              "{%0,%1,%2,%3}, {%4,%5,%6,%7}, {%8,%9}, {%0,%1,%2,%3};\n"
              : "+r"(d[nt][0]), "+r"(d[nt][1]), "+r"(d[nt][2]), "+r"(d[nt][3])
              : "r"(a10), "r"(a11), "r"(a12), "r"(a13), "r"(b.z), "r"(b.w));
        }
      }
    }

    // ---- epilogue: d[row=px][col=oc] -> out[img][oc][orow][px] ----
    const float inv  = 1.0f / (scale_a[0]*scale_w[0]);
    const int   orow = q*2 + nh2;
    const int   px0  = P + g;                   // always < 56
    const bool  hi_ok = (P != 48);              // px0+8 < 56 iff P<48 (warp-uniform)
    float* ob = out + ((size_t)img*KOUT*H + orow)*W;
    #pragma unroll
    for (int nt = 0; nt < 8; ++nt) {
        int oc0 = nt*8 + 2*p;
        float b0v = bias[oc0], b1v = bias[oc0 + 1];
        float* o0 = ob + (size_t)oc0*HW + px0;
        o0[0]  = __int2float_rn(d[nt][0])*inv + b0v;
        o0[HW] = __int2float_rn(d[nt][1])*inv + b1v;
        if (hi_ok) {
            o0[8]    = __int2float_rn(d[nt][2])*inv + b0v;
            o0[HW+8] = __int2float_rn(d[nt][3])*inv + b1v;
        }
    }
}

extern "C" void kernel_launch(void* const* d_in, const int* in_sizes, int n_in,
                              void* d_out, int out_size) {
    const float* x    = (const float*)d_in[0];
    const float* wgt  = (const float*)d_in[1];
    const float* bias = (const float*)d_in[2];
    const float* sa   = (const float*)d_in[3];
    const float* sw   = (const float*)d_in[4];
    const float* zp   = (const float*)d_in[5];
    float* out = (float*)d_out;

    dim3 gq(56, 65);                            // y<64: activations; y==64: weights
    quant_fused_kernel<<<gq, 256>>>(x, wgt, sa, sw, zp);

    cudaFuncSetAttribute(convq_kernel,
        cudaFuncAttributeMaxDynamicSharedMemorySize, SMEM_BYTES);
    dim3 grid(28, N_IMG);                       // 28 row-pairs x 64 images
    convq_kernel<<<grid, 256, SMEM_BYTES>>>(bias, sa, sw, out);
}

// round 9
// speedup vs baseline: 1.5730x; 1.5730x over previous
#include <cuda_runtime.h>
#include <cuda_bf16.h>
#include <cstdint>

#define N_IMG 64
#define CH    64
#define KOUT  64
#define H     56
#define W     56
#define HW    (H*W)

// Quantized activations, bf16, pixel-major:
// elem (((img*56+row)*64 + px)*64 + c); px = j+1, px 0 and 57..63 are zero.
__device__ __nv_bfloat16 g_qab[(size_t)N_IMG*56*64*64];     // 29.4 MB
// Weights bf16 packed as m16n8k16 B-fragments:
// uint4[((nt*9+rs)*2 + kk)*32 + lane] = {b0(ks=2kk), b1(ks=2kk), b0(ks=2kk+1), b1(ks=2kk+1)}
// b0 = {B[k=2p][oc], B[k=2p+1][oc]}, b1 = same k+8;  k = channel within 16-ch kstep
__device__ uint4 g_wqb[8*9*2*32];                            // 73.7 KB

__global__ __launch_bounds__(256)
void quant_fused_kernel(const float* __restrict__ x,
                        const float* __restrict__ w,
                        const float* __restrict__ scale_a,
                        const float* __restrict__ scale_w,
                        const float* __restrict__ zero_point) {
    const int t = threadIdx.x;
    if (blockIdx.y == 64) {
        // ---- weights ----
        const float sw = scale_w[0];
        for (int i = blockIdx.x*256 + t; i < KOUT*576; i += 56*256) {
            int m  = i / 576;                   // oc
            int k  = i - m*576;
            int rs = k >> 6;
            int c  = k & 63;
            int r  = rs/3, s = rs - r*3;
            float wv = w[((m*CH + c)*3 + r)*3 + s];
            int iv = (int)rintf(__fmul_rn(wv, sw));
            iv = ((iv + 128) & 255) - 128;      // two's-complement 8-bit wrap
            int nt = m >> 3;
            int g  = m & 7;
            int ks = c >> 4;
            int kc = c & 15;
            int p  = (kc >> 1) & 3;
            int hi = kc >> 3;
            int e  = kc & 1;
            size_t half_idx =
                ((size_t)(((nt*9 + rs)*2 + (ks>>1))*32 + g*4 + p)*4
                 + ((ks&1)*2 + hi))*2 + e;
            reinterpret_cast<__nv_bfloat16*>(g_wqb)[half_idx] =
                __float2bfloat16((float)iv);
        }
        return;
    }
    // ---- activations: one thread = 16 channels @ one pixel ----
    const int row = blockIdx.x;
    const int img = blockIdx.y;
    const int px  = t >> 2;
    const int cg  = t & 3;
    const int j   = px - 1;
    const float sa = scale_a[0];
    const float zp = zero_point[0];
    uint32_t wd[8];
    #pragma unroll
    for (int i = 0; i < 8; ++i) wd[i] = 0u;
    if ((unsigned)j < (unsigned)W) {
        const float* xb = x + ((size_t)(img*CH + cg*16)*H + row)*W + j;
        #pragma unroll
        for (int h2 = 0; h2 < 8; ++h2) {
            __nv_bfloat162 pk;
            #pragma unroll
            for (int e = 0; e < 2; ++e) {
                float xv = xb[(h2*2 + e)*HW];
                float tq = __fadd_rn(__fmul_rn(xv, sa), -zp);   // match ref rounding
                float v  = fminf(fmaxf(rintf(tq), 0.f), 255.f) + zp;  // q_in + zp
                ((__nv_bfloat16*)&pk)[e] = __float2bfloat16(v);
            }
            wd[h2] = *reinterpret_cast<uint32_t*>(&pk);
        }
    }
    uint4* dst = reinterpret_cast<uint4*>(
        g_qab + ((size_t)((img*56 + row)*64 + px)*64 + cg*16));
    dst[0] = make_uint4(wd[0], wd[1], wd[2], wd[3]);
    dst[1] = make_uint4(wd[4], wd[5], wd[6], wd[7]);
}

#define PSTR 144                      // smem pixel stride bytes (36 words: LDSM conflict-free)
#define SMEM_BYTES (4*68*PSTR)        // 39168 B

__global__ __launch_bounds__(256, 3)
void convq_kernel(const float* __restrict__ bias,
                  const float* __restrict__ scale_a,
                  const float* __restrict__ scale_w,
                  float* __restrict__ out) {
    extern __shared__ uint32_t smem[];
    uint32_t sbase;
    asm("{ .reg .u64 tt; cvta.to.shared.u64 tt, %1; cvt.u32.u64 %0, tt; }"
        : "=r"(sbase) : "l"(smem));

    const int tid  = threadIdx.x;
    const int lane = tid & 31;
    const int warp = tid >> 5;
    const int img  = blockIdx.y;
    const int q    = blockIdx.x;                // output rows 2q, 2q+1

    // ---- stage 4 input rows x 68 px x 128B (bf16) via cp.async, zfill pads ----
    {
        const char* qsrc0 = reinterpret_cast<const char*>(g_qab)
                          + (size_t)img*56*64*64*2;
        #pragma unroll
        for (int it = 0; it < 9; ++it) {
            int i = tid + it*256;               // 0..2175 chunks of 16B
            if (i < 4*68*8) {
                int rowl = i / 544;
                int rem  = i - rowl*544;
                int px   = rem >> 3;
                int c    = rem & 7;
                int ir   = q*2 + rowl - 1;
                int ok   = ((unsigned)ir < (unsigned)H) && (px < 64);
                int sz   = ok ? 16 : 0;
                int irc  = min(max(ir, 0), H-1);
                int pxc  = min(px, 63);
                const char* src = qsrc0 + ((size_t)(irc*64 + pxc)*64 + c*8)*2;
                uint32_t dst = sbase + (rowl*68 + px)*PSTR + c*16;
                asm volatile("cp.async.cg.shared.global [%0], [%1], 16, %2;\n"
                             :: "r"(dst), "l"(src), "r"(sz) : "memory");
            }
        }
        asm volatile("cp.async.commit_group;\n" ::: "memory");
        asm volatile("cp.async.wait_group 0;\n" ::: "memory");
    }
    __syncthreads();

    // ---- GEMM: D[px=16 x oc=64] per warp; A via ldmatrix, B from L1 ----
    const int nh2 = warp >> 2;                  // output row: 2q + nh2
    const int P   = (warp & 3) * 16;            // pixel group base
    const int g   = lane >> 2;
    const int p   = lane & 3;
    // ldmatrix lane address pieces
    const int pxl = (lane & 7) + ((lane >> 3) & 1)*8;
    const int kh  = (lane >> 4) * 16;           // k-half byte offset

    float d[8][4];
    #pragma unroll
    for (int i = 0; i < 8; ++i) { d[i][0]=0.f; d[i][1]=0.f; d[i][2]=0.f; d[i][3]=0.f; }

    const uint4* wq = g_wqb + lane;

    #pragma unroll
    for (int r = 0; r < 3; ++r) {
      #pragma unroll
      for (int s = 0; s < 3; ++s) {
        const int rs = r*3 + s;
        const uint32_t abase = sbase + ((nh2 + r)*68 + P + s + pxl)*PSTR + kh;
        uint32_t a[4][4];
        #pragma unroll
        for (int ks = 0; ks < 4; ++ks) {
            asm volatile(
              "ldmatrix.sync.aligned.m8n8.x4.shared.b16 {%0,%1,%2,%3}, [%4];"
              : "=r"(a[ks][0]), "=r"(a[ks][1]), "=r"(a[ks][2]), "=r"(a[ks][3])
              : "r"(abase + ks*32));
        }
        #pragma unroll
        for (int kk = 0; kk < 2; ++kk) {
            #pragma unroll
            for (int nt = 0; nt < 8; ++nt) {
                uint4 b = wq[(((nt*9 + rs)*2) + kk)*32];    // LDG.128, L1-resident
                asm volatile(
                  "mma.sync.aligned.m16n8k16.row.col.f32.bf16.bf16.f32 "
                  "{%0,%1,%2,%3}, {%4,%5,%6,%7}, {%8,%9}, {%0,%1,%2,%3};\n"
                  : "+f"(d[nt][0]), "+f"(d[nt][1]), "+f"(d[nt][2]), "+f"(d[nt][3])
                  : "r"(a[2*kk][0]), "r"(a[2*kk][1]), "r"(a[2*kk][2]), "r"(a[2*kk][3]),
                    "r"(b.x), "r"(b.y));
                asm volatile(
                  "mma.sync.aligned.m16n8k16.row.col.f32.bf16.bf16.f32 "
                  "{%0,%1,%2,%3}, {%4,%5,%6,%7}, {%8,%9}, {%0,%1,%2,%3};\n"
                  : "+f"(d[nt][0]), "+f"(d[nt][1]), "+f"(d[nt][2]), "+f"(d[nt][3])
                  : "r"(a[2*kk+1][0]), "r"(a[2*kk+1][1]), "r"(a[2*kk+1][2]), "r"(a[2*kk+1][3]),
                    "r"(b.z), "r"(b.w));
            }
        }
      }
    }

    // ---- epilogue: d[row=px][col=oc] -> out[img][oc][orow][px] ----
    const float inv   = 1.0f / (scale_a[0]*scale_w[0]);
    const int   orow  = q*2 + nh2;
    const int   px0   = P + g;                  // < 56
    const bool  hi_ok = (P != 48);              // px0+8 valid iff P<48 (warp-uniform)
    float* ob = out + ((size_t)img*KOUT*H + orow)*W;
    #pragma unroll
    for (int nt = 0; nt < 8; ++nt) {
        int oc0 = nt*8 + 2*p;
        float b0v = bias[oc0], b1v = bias[oc0 + 1];
        float* o0 = ob + (size_t)oc0*HW + px0;
        o0[0]  = d[nt][0]*inv + b0v;
        o0[HW] = d[nt][1]*inv + b1v;
        if (hi_ok) {
            o0[8]    = d[nt][2]*inv + b0v;
            o0[HW+8] = d[nt][3]*inv + b1v;
        }
    }
}

extern "C" void kernel_launch(void* const* d_in, const int* in_sizes, int n_in,
                              void* d_out, int out_size) {
    const float* x    = (const float*)d_in[0];
    const float* wgt  = (const float*)d_in[1];
    const float* bias = (const float*)d_in[2];
    const float* sa   = (const float*)d_in[3];
    const float* sw   = (const float*)d_in[4];
    const float* zp   = (const float*)d_in[5];
    float* out = (float*)d_out;

    dim3 gq(56, 65);                            // y<64: activations; y==64: weights
    quant_fused_kernel<<<gq, 256>>>(x, wgt, sa, sw, zp);

    cudaFuncSetAttribute(convq_kernel,
        cudaFuncAttributeMaxDynamicSharedMemorySize, SMEM_BYTES);
    dim3 grid(28, N_IMG);                       // 28 row-pairs x 64 images
    convq_kernel<<<grid, 256, SMEM_BYTES>>>(bias, sa, sw, out);
}

// round 10
// speedup vs baseline: 1.7710x; 1.1259x over previous
#include <cuda_runtime.h>
#include <cuda_bf16.h>
#include <cstdint>

#define N_IMG 64
#define CH    64
#define KOUT  64
#define H     56
#define W     56
#define HW    (H*W)

// Quantized activations, bf16, pixel-major:
// elem (((img*56+row)*64 + px)*64 + c); px = j+1, px 0 and 57..63 are zero.
__device__ __nv_bfloat16 g_qab[(size_t)N_IMG*56*64*64];     // 29.4 MB
// Weights bf16 packed as m16n8k16 B-fragments:
// uint4[((nt*9+rs)*2 + kk)*32 + lane] = {b0(ks=2kk), b1(ks=2kk), b0(ks=2kk+1), b1(ks=2kk+1)}
__device__ uint4 g_wqb[8*9*2*32];                            // 73.7 KB

__global__ __launch_bounds__(256)
void quant_fused_kernel(const float* __restrict__ x,
                        const float* __restrict__ w,
                        const float* __restrict__ scale_a,
                        const float* __restrict__ scale_w,
                        const float* __restrict__ zero_point) {
    const int t = threadIdx.x;
    if (blockIdx.y == 64) {
        // ---- weights ----
        const float sw = scale_w[0];
        for (int i = blockIdx.x*256 + t; i < KOUT*576; i += 56*256) {
            int m  = i / 576;                   // oc
            int k  = i - m*576;
            int rs = k >> 6;
            int c  = k & 63;
            int r  = rs/3, s = rs - r*3;
            float wv = w[((m*CH + c)*3 + r)*3 + s];
            int iv = (int)rintf(__fmul_rn(wv, sw));
            iv = ((iv + 128) & 255) - 128;      // two's-complement 8-bit wrap
            int nt = m >> 3;
            int g  = m & 7;
            int ks = c >> 4;
            int kc = c & 15;
            int p  = (kc >> 1) & 3;
            int hi = kc >> 3;
            int e  = kc & 1;
            size_t half_idx =
                ((size_t)(((nt*9 + rs)*2 + (ks>>1))*32 + g*4 + p)*4
                 + ((ks&1)*2 + hi))*2 + e;
            reinterpret_cast<__nv_bfloat16*>(g_wqb)[half_idx] =
                __float2bfloat16((float)iv);
        }
        return;
    }
    // ---- activations: one thread = 16 channels @ one pixel ----
    const int row = blockIdx.x;
    const int img = blockIdx.y;
    const int px  = t >> 2;
    const int cg  = t & 3;
    const int j   = px - 1;
    const float sa = scale_a[0];
    const float zp = zero_point[0];
    uint32_t wd[8];
    #pragma unroll
    for (int i = 0; i < 8; ++i) wd[i] = 0u;
    if ((unsigned)j < (unsigned)W) {
        const float* xb = x + ((size_t)(img*CH + cg*16)*H + row)*W + j;
        #pragma unroll
        for (int h2 = 0; h2 < 8; ++h2) {
            __nv_bfloat162 pk;
            #pragma unroll
            for (int e = 0; e < 2; ++e) {
                float xv = xb[(h2*2 + e)*HW];
                float tq = __fadd_rn(__fmul_rn(xv, sa), -zp);   // match ref rounding
                float v  = fminf(fmaxf(rintf(tq), 0.f), 255.f) + zp;  // q_in + zp
                ((__nv_bfloat16*)&pk)[e] = __float2bfloat16(v);
            }
            wd[h2] = *reinterpret_cast<uint32_t*>(&pk);
        }
    }
    uint4* dst = reinterpret_cast<uint4*>(
        g_qab + ((size_t)((img*56 + row)*64 + px)*64 + cg*16));
    dst[0] = make_uint4(wd[0], wd[1], wd[2], wd[3]);
    dst[1] = make_uint4(wd[4], wd[5], wd[6], wd[7]);
}

#define PSTR 144                      // smem pixel stride bytes (LDSM conflict-free)
#define SMEM_BYTES (6*68*PSTR)        // 58752 B

__global__ __launch_bounds__(256, 2)
void convq_kernel(const float* __restrict__ bias,
                  const float* __restrict__ scale_a,
                  const float* __restrict__ scale_w,
                  float* __restrict__ out) {
    extern __shared__ uint32_t smem[];
    uint32_t sbase;
    asm("{ .reg .u64 tt; cvta.to.shared.u64 tt, %1; cvt.u32.u64 %0, tt; }"
        : "=r"(sbase) : "l"(smem));

    const int tid  = threadIdx.x;
    const int lane = tid & 31;
    const int warp = tid >> 5;
    const int img  = blockIdx.y;
    const int q    = blockIdx.x;                // output rows 4q..4q+3

    // ---- stage 6 input rows x 68 px x 128B (bf16) via cp.async, zfill pads ----
    {
        const char* qsrc0 = reinterpret_cast<const char*>(g_qab)
                          + (size_t)img*56*64*64*2;
        #pragma unroll
        for (int it = 0; it < 13; ++it) {
            int i = tid + it*256;               // 16B chunks, need 6*544=3264
            if (i < 6*544) {
                int rowl = i / 544;
                int rem  = i - rowl*544;
                int px   = rem >> 3;
                int c    = rem & 7;
                int ir   = q*4 + rowl - 1;
                int ok   = ((unsigned)ir < (unsigned)H) && (px < 64);
                int sz   = ok ? 16 : 0;
                int irc  = min(max(ir, 0), H-1);
                int pxc  = min(px, 63);
                const char* src = qsrc0 + ((size_t)(irc*64 + pxc)*64 + c*8)*2;
                uint32_t dst = sbase + (rowl*68 + px)*PSTR + c*16;
                asm volatile("cp.async.cg.shared.global [%0], [%1], 16, %2;\n"
                             :: "r"(dst), "l"(src), "r"(sz) : "memory");
            }
        }
        asm volatile("cp.async.commit_group;\n" ::: "memory");
        asm volatile("cp.async.wait_group 0;\n" ::: "memory");
    }
    __syncthreads();

    // ---- GEMM: D[px=32 x oc=64] per warp; A via ldmatrix, B from L1 ----
    const int row = warp >> 1;                  // output row: 4q + row
    const int P   = (warp & 1) * 32;            // pixel group base (0 or 32)
    const int g   = lane >> 2;
    const int p   = lane & 3;
    const int pxl = (lane & 7) + ((lane >> 3) & 1)*8;   // ldmatrix row-in-group
    const int kh  = (lane >> 4) * 16;                   // k-half byte offset

    float d[2][8][4];
    #pragma unroll
    for (int h = 0; h < 2; ++h)
      #pragma unroll
      for (int i = 0; i < 8; ++i) {
        d[h][i][0]=0.f; d[h][i][1]=0.f; d[h][i][2]=0.f; d[h][i][3]=0.f;
      }

    const uint4* wq = g_wqb + lane;

    #pragma unroll
    for (int r = 0; r < 3; ++r) {
      #pragma unroll
      for (int s = 0; s < 3; ++s) {
        const int rs = r*3 + s;
        uint32_t a[2][4][4];
        #pragma unroll
        for (int h = 0; h < 2; ++h) {
            const uint32_t abase =
                sbase + ((row + r)*68 + P + h*16 + s + pxl)*PSTR + kh;
            #pragma unroll
            for (int ks = 0; ks < 4; ++ks) {
                asm volatile(
                  "ldmatrix.sync.aligned.m8n8.x4.shared.b16 {%0,%1,%2,%3}, [%4];"
                  : "=r"(a[h][ks][0]), "=r"(a[h][ks][1]),
                    "=r"(a[h][ks][2]), "=r"(a[h][ks][3])
                  : "r"(abase + ks*32));
            }
        }
        #pragma unroll
        for (int kk = 0; kk < 2; ++kk) {
            #pragma unroll
            for (int nt = 0; nt < 8; ++nt) {
                uint4 b = wq[(((nt*9 + rs)*2) + kk)*32];    // LDG.128, L1-resident
                #pragma unroll
                for (int h = 0; h < 2; ++h) {
                    asm volatile(
                      "mma.sync.aligned.m16n8k16.row.col.f32.bf16.bf16.f32 "
                      "{%0,%1,%2,%3}, {%4,%5,%6,%7}, {%8,%9}, {%0,%1,%2,%3};\n"
                      : "+f"(d[h][nt][0]), "+f"(d[h][nt][1]),
                        "+f"(d[h][nt][2]), "+f"(d[h][nt][3])
                      : "r"(a[h][2*kk][0]), "r"(a[h][2*kk][1]),
                        "r"(a[h][2*kk][2]), "r"(a[h][2*kk][3]),
                        "r"(b.x), "r"(b.y));
                    asm volatile(
                      "mma.sync.aligned.m16n8k16.row.col.f32.bf16.bf16.f32 "
                      "{%0,%1,%2,%3}, {%4,%5,%6,%7}, {%8,%9}, {%0,%1,%2,%3};\n"
                      : "+f"(d[h][nt][0]), "+f"(d[h][nt][1]),
                        "+f"(d[h][nt][2]), "+f"(d[h][nt][3])
                      : "r"(a[h][2*kk+1][0]), "r"(a[h][2*kk+1][1]),
                        "r"(a[h][2*kk+1][2]), "r"(a[h][2*kk+1][3]),
                        "r"(b.z), "r"(b.w));
                }
            }
        }
      }
    }

    // ---- epilogue: d[h][nt] -> out[img][oc][orow][px] ----
    const float inv  = 1.0f / (scale_a[0]*scale_w[0]);
    const int   orow = q*4 + row;
    float* ob = out + ((size_t)img*KOUT*H + orow)*W;
    #pragma unroll
    for (int h = 0; h < 2; ++h) {
        const int  px0   = P + h*16 + g;        // 0..55 always valid
        const bool hi_ok = (P + h*16) != 48;    // px0+8 < 56 (warp-uniform)
        #pragma unroll
        for (int nt = 0; nt < 8; ++nt) {
            int oc0 = nt*8 + 2*p;
            float b0v = bias[oc0], b1v = bias[oc0 + 1];
            float* o0 = ob + (size_t)oc0*HW + px0;
            o0[0]  = d[h][nt][0]*inv + b0v;
            o0[HW] = d[h][nt][1]*inv + b1v;
            if (hi_ok) {
                o0[8]    = d[h][nt][2]*inv + b0v;
                o0[HW+8] = d[h][nt][3]*inv + b1v;
            }
        }
    }
}

extern "C" void kernel_launch(void* const* d_in, const int* in_sizes, int n_in,
                              void* d_out, int out_size) {
    const float* x    = (const float*)d_in[0];
    const float* wgt  = (const float*)d_in[1];
    const float* bias = (const float*)d_in[2];
    const float* sa   = (const float*)d_in[3];
    const float* sw   = (const float*)d_in[4];
    const float* zp   = (const float*)d_in[5];
    float* out = (float*)d_out;

    dim3 gq(56, 65);                            // y<64: activations; y==64: weights
    quant_fused_kernel<<<gq, 256>>>(x, wgt, sa, sw, zp);

    cudaFuncSetAttribute(convq_kernel,
        cudaFuncAttributeMaxDynamicSharedMemorySize, SMEM_BYTES);
    dim3 grid(14, N_IMG);                       // 14 row-quads x 64 images
    convq_kernel<<<grid, 256, SMEM_BYTES>>>(bias, sa, sw, out);
}

// round 11
// speedup vs baseline: 2.1357x; 1.2059x over previous
#include <cuda_runtime.h>
#include <cuda_bf16.h>
#include <cstdint>

#define N_IMG 64
#define CH    64
#define KOUT  64
#define H     56
#define W     56
#define HW    (H*W)

// Quantized activations, bf16, pixel-major:
// elem (((img*56+row)*64 + px)*64 + c); px = j+1, px 0 and 57..63 are zero.
__device__ __nv_bfloat16 g_qab[(size_t)N_IMG*56*64*64];     // 29.4 MB
// Weights bf16 packed as m16n8k16 B-fragments:
// uint4[((nt*9+rs)*2 + kk)*32 + lane] = {b0(ks=2kk), b1(ks=2kk), b0(ks=2kk+1), b1(ks=2kk+1)}
__device__ uint4 g_wqb[8*9*2*32];                            // 73.7 KB

__global__ __launch_bounds__(256)
void quant_fused_kernel(const float* __restrict__ x,
                        const float* __restrict__ w,
                        const float* __restrict__ scale_a,
                        const float* __restrict__ scale_w,
                        const float* __restrict__ zero_point) {
    const int t = threadIdx.x;
    if (blockIdx.y == 64) {
        // ---- weights ----
        const float sw = scale_w[0];
        for (int i = blockIdx.x*256 + t; i < KOUT*576; i += 56*256) {
            int m  = i / 576;                   // oc
            int k  = i - m*576;
            int rs = k >> 6;
            int c  = k & 63;
            int r  = rs/3, s = rs - r*3;
            float wv = w[((m*CH + c)*3 + r)*3 + s];
            int iv = (int)rintf(__fmul_rn(wv, sw));
            iv = ((iv + 128) & 255) - 128;      // two's-complement 8-bit wrap
            int nt = m >> 3;
            int g  = m & 7;
            int ks = c >> 4;
            int kc = c & 15;
            int p  = (kc >> 1) & 3;
            int hi = kc >> 3;
            int e  = kc & 1;
            size_t half_idx =
                ((size_t)(((nt*9 + rs)*2 + (ks>>1))*32 + g*4 + p)*4
                 + ((ks&1)*2 + hi))*2 + e;
            reinterpret_cast<__nv_bfloat16*>(g_wqb)[half_idx] =
                __float2bfloat16((float)iv);
        }
        return;
    }
    // ---- activations: one thread = 16 channels @ one pixel ----
    const int row = blockIdx.x;
    const int img = blockIdx.y;
    const int px  = t >> 2;
    const int cg  = t & 3;
    const int j   = px - 1;
    const float sa = scale_a[0];
    const float zp = zero_point[0];
    uint32_t wd[8];
    #pragma unroll
    for (int i = 0; i < 8; ++i) wd[i] = 0u;
    if ((unsigned)j < (unsigned)W) {
        const float* xb = x + ((size_t)(img*CH + cg*16)*H + row)*W + j;
        #pragma unroll
        for (int h2 = 0; h2 < 8; ++h2) {
            __nv_bfloat162 pk;
            #pragma unroll
            for (int e = 0; e < 2; ++e) {
                float xv = xb[(h2*2 + e)*HW];
                float tq = __fadd_rn(__fmul_rn(xv, sa), -zp);   // match ref rounding
                float v  = fminf(fmaxf(rintf(tq), 0.f), 255.f) + zp;  // q_in + zp
                ((__nv_bfloat16*)&pk)[e] = __float2bfloat16(v);
            }
            wd[h2] = *reinterpret_cast<uint32_t*>(&pk);
        }
    }
    uint4* dst = reinterpret_cast<uint4*>(
        g_qab + ((size_t)((img*56 + row)*64 + px)*64 + cg*16));
    dst[0] = make_uint4(wd[0], wd[1], wd[2], wd[3]);
    dst[1] = make_uint4(wd[4], wd[5], wd[6], wd[7]);
}

#define PSTR 144                      // smem pixel stride bytes (LDSM conflict-free)
#define SMEM_BYTES (6*68*PSTR)        // 58752 B

__global__ __launch_bounds__(128, 2)
void convq_kernel(const float* __restrict__ bias,
                  const float* __restrict__ scale_a,
                  const float* __restrict__ scale_w,
                  float* __restrict__ out) {
    extern __shared__ uint32_t smem[];
    uint32_t sbase;
    asm("{ .reg .u64 tt; cvta.to.shared.u64 tt, %1; cvt.u32.u64 %0, tt; }"
        : "=r"(sbase) : "l"(smem));

    const int tid  = threadIdx.x;
    const int lane = tid & 31;
    const int warp = tid >> 5;
    const int img  = blockIdx.y;
    const int q    = blockIdx.x;                // output rows 4q..4q+3

    // ---- stage 6 input rows x 68 px x 128B (bf16) via cp.async, zfill pads ----
    {
        const char* qsrc0 = reinterpret_cast<const char*>(g_qab)
                          + (size_t)img*56*64*64*2;
        #pragma unroll
        for (int it = 0; it < 26; ++it) {
            int i = tid + it*128;               // 16B chunks, need 6*544=3264
            if (i < 6*544) {
                int rowl = i / 544;
                int rem  = i - rowl*544;
                int px   = rem >> 3;
                int c    = rem & 7;
                int ir   = q*4 + rowl - 1;
                int ok   = ((unsigned)ir < (unsigned)H) && (px < 64);
                int sz   = ok ? 16 : 0;
                int irc  = min(max(ir, 0), H-1);
                int pxc  = min(px, 63);
                const char* src = qsrc0 + ((size_t)(irc*64 + pxc)*64 + c*8)*2;
                uint32_t dst = sbase + (rowl*68 + px)*PSTR + c*16;
                asm volatile("cp.async.cg.shared.global [%0], [%1], 16, %2;\n"
                             :: "r"(dst), "l"(src), "r"(sz) : "memory");
            }
        }
        asm volatile("cp.async.commit_group;\n" ::: "memory");
        asm volatile("cp.async.wait_group 0;\n" ::: "memory");
    }
    __syncthreads();

    // ---- GEMM: D[px=64 x oc=64] per warp (one full output row) ----
    const int g   = lane >> 2;
    const int p   = lane & 3;
    const int pxl = (lane & 7) + ((lane >> 3) & 1)*8;   // ldmatrix row-in-group
    const int kh  = (lane >> 4) * 16;                   // k-half byte offset

    float d[4][8][4];
    #pragma unroll
    for (int h = 0; h < 4; ++h)
      #pragma unroll
      for (int i = 0; i < 8; ++i) {
        d[h][i][0]=0.f; d[h][i][1]=0.f; d[h][i][2]=0.f; d[h][i][3]=0.f;
      }

    const uint4* wq = g_wqb + lane;

    #pragma unroll
    for (int r = 0; r < 3; ++r) {
      #pragma unroll
      for (int s = 0; s < 3; ++s) {
        const int rs = r*3 + s;
        uint32_t a[4][4][4];
        #pragma unroll
        for (int h = 0; h < 4; ++h) {
            const uint32_t abase =
                sbase + ((warp + r)*68 + h*16 + s + pxl)*PSTR + kh;
            #pragma unroll
            for (int ks = 0; ks < 4; ++ks) {
                asm volatile(
                  "ldmatrix.sync.aligned.m8n8.x4.shared.b16 {%0,%1,%2,%3}, [%4];"
                  : "=r"(a[h][ks][0]), "=r"(a[h][ks][1]),
                    "=r"(a[h][ks][2]), "=r"(a[h][ks][3])
                  : "r"(abase + ks*32));
            }
        }
        #pragma unroll
        for (int kk = 0; kk < 2; ++kk) {
            #pragma unroll
            for (int nt = 0; nt < 8; ++nt) {
                uint4 b = wq[(((nt*9 + rs)*2) + kk)*32];    // LDG.128, L1-resident
                #pragma unroll
                for (int h = 0; h < 4; ++h) {
                    asm volatile(
                      "mma.sync.aligned.m16n8k16.row.col.f32.bf16.bf16.f32 "
                      "{%0,%1,%2,%3}, {%4,%5,%6,%7}, {%8,%9}, {%0,%1,%2,%3};\n"
                      : "+f"(d[h][nt][0]), "+f"(d[h][nt][1]),
                        "+f"(d[h][nt][2]), "+f"(d[h][nt][3])
                      : "r"(a[h][2*kk][0]), "r"(a[h][2*kk][1]),
                        "r"(a[h][2*kk][2]), "r"(a[h][2*kk][3]),
                        "r"(b.x), "r"(b.y));
                    asm volatile(
                      "mma.sync.aligned.m16n8k16.row.col.f32.bf16.bf16.f32 "
                      "{%0,%1,%2,%3}, {%4,%5,%6,%7}, {%8,%9}, {%0,%1,%2,%3};\n"
                      : "+f"(d[h][nt][0]), "+f"(d[h][nt][1]),
                        "+f"(d[h][nt][2]), "+f"(d[h][nt][3])
                      : "r"(a[h][2*kk+1][0]), "r"(a[h][2*kk+1][1]),
                        "r"(a[h][2*kk+1][2]), "r"(a[h][2*kk+1][3]),
                        "r"(b.z), "r"(b.w));
                }
            }
        }
      }
    }

    // ---- epilogue: d[h][nt] -> out[img][oc][orow][px] ----
    const float inv  = 1.0f / (scale_a[0]*scale_w[0]);
    const int   orow = q*4 + warp;
    float* ob = out + ((size_t)img*KOUT*H + orow)*W;
    #pragma unroll
    for (int h = 0; h < 4; ++h) {
        const int  px0   = h*16 + g;            // 0..55 always valid
        const bool hi_ok = (h != 3);            // px0+8 < 56 (warp-uniform)
        #pragma unroll
        for (int nt = 0; nt < 8; ++nt) {
            int oc0 = nt*8 + 2*p;
            float b0v = bias[oc0], b1v = bias[oc0 + 1];
            float* o0 = ob + (size_t)oc0*HW + px0;
            o0[0]  = d[h][nt][0]*inv + b0v;
            o0[HW] = d[h][nt][1]*inv + b1v;
            if (hi_ok) {
                o0[8]    = d[h][nt][2]*inv + b0v;
                o0[HW+8] = d[h][nt][3]*inv + b1v;
            }
        }
    }
}

extern "C" void kernel_launch(void* const* d_in, const int* in_sizes, int n_in,
                              void* d_out, int out_size) {
    const float* x    = (const float*)d_in[0];
    const float* wgt  = (const float*)d_in[1];
    const float* bias = (const float*)d_in[2];
    const float* sa   = (const float*)d_in[3];
    const float* sw   = (const float*)d_in[4];
    const float* zp   = (const float*)d_in[5];
    float* out = (float*)d_out;

    dim3 gq(56, 65);                            // y<64: activations; y==64: weights
    quant_fused_kernel<<<gq, 256>>>(x, wgt, sa, sw, zp);

    cudaFuncSetAttribute(convq_kernel,
        cudaFuncAttributeMaxDynamicSharedMemorySize, SMEM_BYTES);
    dim3 grid(14, N_IMG);                       // 14 row-quads x 64 images
    convq_kernel<<<grid, 128, SMEM_BYTES>>>(bias, sa, sw, out);
}